// round 1
// baseline (speedup 1.0000x reference)
#include <cuda_runtime.h>
#include <cuda_bf16.h>
#include <cstdint>

// MaxUnpool2D as a coalesced gather.
// x:    [B=8, H=128, W=128, C=64] float32
// mask: [B, H, W, C] int32, flat index into [HOUT*WOUT*C] per batch
// out:  [B, HOUT=256, WOUT=256, C] float32
//
// Each pooled cell scatters into its private 2x2 window -> indices unique,
// so gather semantics (exact-match test) reproduce scatter_nd-add exactly.

static constexpr int Bc    = 8;
static constexpr int Hc    = 128;
static constexpr int Wc    = 128;
static constexpr int Cc    = 64;
static constexpr int HOUT  = 256;
static constexpr int WOUT  = 256;

__global__ __launch_bounds__(256) void max_unpool_gather(
    const float4* __restrict__ x4,
    const int4*   __restrict__ m4,
    float4*       __restrict__ out4,
    int n4)  // number of float4 output groups
{
    int idx = blockIdx.x * blockDim.x + threadIdx.x;
    if (idx >= n4) return;

    // Decompose: idx -> (b, ho, wo, c4). All power-of-two dims.
    // layout: b * (HOUT*WOUT*C/4) + ho * (WOUT*C/4) + wo * (C/4) + c4
    int c4 = idx & 15;             // C/4 = 16
    int t  = idx >> 4;
    int wo = t & (WOUT - 1);       // 256
    t >>= 8;
    int ho = t & (HOUT - 1);       // 256
    int b  = t >> 8;

    int h = ho >> 1;
    int w = wo >> 1;
    int c = c4 << 2;

    // pooled-space float4/int4 offset
    int pooled4 = ((b * Hc + h) * Wc + w) * (Cc / 4) + c4;

    int4   m = __ldg(&m4[pooled4]);
    float4 v = __ldg(&x4[pooled4]);

    int flat = (ho * WOUT + wo) * Cc + c;  // expected argmax flat index for lane .x

    float4 o;
    o.x = (m.x == flat    ) ? v.x : 0.0f;
    o.y = (m.y == flat + 1) ? v.y : 0.0f;
    o.z = (m.z == flat + 2) ? v.z : 0.0f;
    o.w = (m.w == flat + 3) ? v.w : 0.0f;

    out4[idx] = o;
}

extern "C" void kernel_launch(void* const* d_in, const int* in_sizes, int n_in,
                              void* d_out, int out_size)
{
    const float4* x4 = (const float4*)d_in[0];   // input_pool float32
    const int4*   m4 = (const int4*)  d_in[1];   // pool_mask int32
    float4*       o4 = (float4*)d_out;

    int n4 = out_size / 4;  // 33,554,432 / 4 = 8,388,608
    int threads = 256;
    int blocks = (n4 + threads - 1) / threads;
    max_unpool_gather<<<blocks, threads>>>(x4, m4, o4, n4);
}

// round 4
// speedup vs baseline: 1.0954x; 1.0954x over previous
#include <cuda_runtime.h>
#include <cuda_bf16.h>
#include <cstdint>

// MaxUnpool2D, scatter-shaped: one thread per pooled float4 group.
// Each thread reads its pooled mask4/val4 ONCE and writes the entire
// 2x2 output window (4 coalesced float4 stores). Indices are unique per
// pooled cell (argmax within its own 2x2 window), so no atomics needed
// and every output element is written exactly once.
//
// x:    [B=8, H=128, W=128, C=64] float32
// mask: [B, H, W, C] int32 (flat idx into [HOUT*WOUT*C] per batch)
// out:  [B, 256, 256, C] float32

static constexpr int Bc   = 8;
static constexpr int Hc   = 128;
static constexpr int Wc   = 128;
static constexpr int Cc   = 64;
static constexpr int HOUT = 256;
static constexpr int WOUT = 256;
static constexpr int C4   = Cc / 4;          // 16
static constexpr int N4   = Bc * Hc * Wc * C4;  // 2,097,152 pooled float4 groups

__global__ __launch_bounds__(256) void max_unpool_scatter4(
    const float4* __restrict__ x4,
    const int4*   __restrict__ m4,
    float4*       __restrict__ out4)
{
    int idx = blockIdx.x * blockDim.x + threadIdx.x;
    if (idx >= N4) return;

    // pooled layout == idx layout: b,h,w,c4 (all pow2)
    int c4 = idx & (C4 - 1);
    int t  = idx >> 4;
    int w  = t & (Wc - 1);
    t >>= 7;
    int h  = t & (Hc - 1);
    int b  = t >> 7;

    int4   m = __ldcs(&m4[idx]);
    float4 v = __ldcs(&x4[idx]);

    int c  = c4 << 2;
    int ho = h << 1;
    int wo = w << 1;

    // output float4 offset base: ((b*HOUT + ho)*WOUT + wo)*C4 + c4
    int obase = ((b * HOUT + ho) * WOUT + wo) * C4 + c4;

#pragma unroll
    for (int dh = 0; dh < 2; ++dh) {
#pragma unroll
        for (int dw = 0; dw < 2; ++dw) {
            int flat = (((ho + dh) * WOUT) + (wo + dw)) * Cc + c;  // lane .x expected idx
            float4 o;
            o.x = (m.x == flat    ) ? v.x : 0.0f;
            o.y = (m.y == flat + 1) ? v.y : 0.0f;
            o.z = (m.z == flat + 2) ? v.z : 0.0f;
            o.w = (m.w == flat + 3) ? v.w : 0.0f;
            __stcs(&out4[obase + dh * (WOUT * C4) + dw * C4], o);
        }
    }
}

extern "C" void kernel_launch(void* const* d_in, const int* in_sizes, int n_in,
                              void* d_out, int out_size)
{
    const float4* x4 = (const float4*)d_in[0];   // input_pool float32
    const int4*   m4 = (const int4*)  d_in[1];   // pool_mask int32
    float4*       o4 = (float4*)d_out;

    int threads = 256;
    int blocks  = (N4 + threads - 1) / threads;  // 8192
    max_unpool_scatter4<<<blocks, threads>>>(x4, m4, o4);
}